// round 7
// baseline (speedup 1.0000x reference)
#include <cuda_runtime.h>

#define V_NODES 2048
#define D_F     128
#define NBLK    128            // scatter blocks (phase 2)
#define NPB     16             // nodes per scatter block
#define NK      73             // 1 + 8 + 64 output coefficient rows
#define CHUNKS  256            // row chunks for degree partial sums
#define ROWS_PER 8             // rows per chunk
#define GRID    512            // fused-kernel grid (all co-resident: 6 blk/SM cap)

// Scratch (static device globals — no allocation allowed; zero-init at load)
__device__ float g_degp[CHUNKS * V_NODES];     // per-chunk column partial sums
__device__ float g_partial[NBLK * NK * D_F];   // block-major scattering partials
__device__ int   g_ct;                         // barrier counter (monotonic across replays)

// ---------------------------------------------------------------------------
// Fused kernel: phase 1 = column partial sums of W (symmetric: col == row sum)
// across all 512 blocks; software grid barrier; phase 2 = scattering on
// blocks 0..127. Barrier is epoch-based: each call adds exactly GRID to g_ct,
// so the counter stays a multiple of GRID at call boundaries — deterministic
// and safe across graph replays.
// ---------------------------------------------------------------------------
__global__ void __launch_bounds__(256) fused_kernel(const float* __restrict__ W,
                                                    const float* __restrict__ f) {
    __shared__ float lam_s[8][NPB];
    __shared__ float deg_sh[NPB];
    __shared__ float comb[NK][D_F];
    __shared__ int   s_target;

    const int bid = blockIdx.x;
    const int tid = threadIdx.x;

    // ---------------- Phase 1: degree partials ----------------
    {
        const int g  = bid & 1;
        const int rc = bid >> 1;
        const int c4 = g * 256 + tid;              // float4 column index [0,512)
        const float4* base = (const float4*)W + (size_t)rc * ROWS_PER * 512 + c4;

        float4 v0 = base[0 * 512];
        float4 v1 = base[1 * 512];
        float4 v2 = base[2 * 512];
        float4 v3 = base[3 * 512];
        float4 v4 = base[4 * 512];
        float4 v5 = base[5 * 512];
        float4 v6 = base[6 * 512];
        float4 v7 = base[7 * 512];

        float4 a;
        a.x = ((v0.x + v1.x) + (v2.x + v3.x)) + ((v4.x + v5.x) + (v6.x + v7.x));
        a.y = ((v0.y + v1.y) + (v2.y + v3.y)) + ((v4.y + v5.y) + (v6.y + v7.y));
        a.z = ((v0.z + v1.z) + (v2.z + v3.z)) + ((v4.z + v5.z) + (v6.z + v7.z));
        a.w = ((v0.w + v1.w) + (v2.w + v3.w)) + ((v4.w + v5.w) + (v6.w + v7.w));

        ((float4*)(g_degp + (size_t)rc * V_NODES))[c4] = a;
    }

    // ---------------- Grid barrier ----------------
    __threadfence();                 // publish g_degp before arriving
    __syncthreads();
    if (tid == 0) {
        int old = atomicAdd(&g_ct, 1);
        s_target = (old / GRID + 1) * GRID;
    }
    __syncthreads();
    if (bid >= NBLK) return;         // non-scatter blocks just arrive and exit
    if (tid == 0) {
        while (*(volatile int*)&g_ct < s_target)
            __nanosleep(64);
    }
    __syncthreads();
    __threadfence();                 // acquire: see all blocks' g_degp writes

    // ---------------- Phase 2: scattering (blocks 0..127) ----------------
    const int b = bid;
    const int half = tid >> 7;       // 0 or 1
    const int d = tid & 127;         // feature index

    // Finalize degrees for this block's 16 nodes (sum 256 chunk partials).
    {
        const int n = tid >> 4;      // node within tile [0,16)
        const int sub = tid & 15;
        float s = 0.f;
#pragma unroll
        for (int k = 0; k < 16; k++)
            s += g_degp[(size_t)(sub + 16 * k) * V_NODES + b * NPB + n];
#pragma unroll
        for (int off = 8; off; off >>= 1)
            s += __shfl_down_sync(0xffffffffu, s, off, 16);
        if (sub == 0) deg_sh[n] = s;
    }
    __syncthreads();

    if (tid < NPB) {
        float dg = deg_sh[tid];
        float inv = 1.0f / fmaxf(1.0f, dg);       // dhalf^2 with clamp
        float E = fabsf(dg * inv);                // |eigenvalue| for this node
        float logE = logf(E);
        const float Ac = 0.34657359027997264f;    // A = 3*ln(2)/6
        float s = 1.125f;                         // (R/2)*sum(d^2) + (R/2)*d0^2
#pragma unroll
        for (int j = 2; j <= 8; j++) {
            float x = logE - Ac * (float)(j - 1) * (1.0f / 3.0f);
            float w = 0.0f;
            if (x > -Ac && x <= 0.0f)
                w = 0.5f - 0.5f * cosf(x * (6.283185307179586f / Ac));
            lam_s[j - 1][tid] = w;
            s -= w * w;
        }
        lam_s[0][tid] = sqrtf(fmaxf(s, 0.0f));    // scaling function
    }
    __syncthreads();

    // Each half handles 8 nodes x 1 feature per thread.
    const int n0 = half * 8;
    float fv[8];
#pragma unroll
    for (int n = 0; n < 8; n++)
        fv[n] = f[(size_t)(b * NPB + n0 + n) * D_F + d];

    float acc[NK];
#pragma unroll
    for (int k = 0; k < NK; k++) acc[k] = 0.f;

#pragma unroll
    for (int n = 0; n < 8; n++) {
        float v = fv[n];
        float af = fabsf(v);
        acc[0] += v;
        float l[8];
#pragma unroll
        for (int j = 0; j < 8; j++) l[j] = lam_s[j][n0 + n];   // smem broadcast
#pragma unroll
        for (int j = 0; j < 8; j++) acc[1 + j] += l[j] * af;
#pragma unroll
        for (int j1 = 0; j1 < 8; j1++) {
            float t = l[j1] * af;
#pragma unroll
            for (int j2 = 0; j2 < 8; j2++)
                acc[9 + j1 * 8 + j2] += l[j2] * t;
        }
    }

    // Combine halves through smem, half 1 stores.
    if (half == 0) {
#pragma unroll
        for (int k = 0; k < NK; k++) comb[k][d] = acc[k];
    }
    __syncthreads();
    if (half == 1) {
        float* p = g_partial + (size_t)b * (NK * D_F) + d;
#pragma unroll
        for (int k = 0; k < NK; k++)
            p[k * D_F] = acc[k] + comb[k][d];
    }
}

// ---------------------------------------------------------------------------
// Kernel 2: sum partials over the 128 scatter blocks, scale by 1/V.
// ---------------------------------------------------------------------------
__global__ void __launch_bounds__(256) reduce_kernel(float* __restrict__ out) {
    const int i = blockIdx.x * 256 + threadIdx.x;
    if (i >= NK * D_F) return;
    float s0 = 0.f, s1 = 0.f, s2 = 0.f, s3 = 0.f;
    float s4 = 0.f, s5 = 0.f, s6 = 0.f, s7 = 0.f;
#pragma unroll
    for (int b = 0; b < NBLK; b += 8) {
        s0 += g_partial[(b + 0) * (NK * D_F) + i];
        s1 += g_partial[(b + 1) * (NK * D_F) + i];
        s2 += g_partial[(b + 2) * (NK * D_F) + i];
        s3 += g_partial[(b + 3) * (NK * D_F) + i];
        s4 += g_partial[(b + 4) * (NK * D_F) + i];
        s5 += g_partial[(b + 5) * (NK * D_F) + i];
        s6 += g_partial[(b + 6) * (NK * D_F) + i];
        s7 += g_partial[(b + 7) * (NK * D_F) + i];
    }
    out[i] = (((s0 + s1) + (s2 + s3)) + ((s4 + s5) + (s6 + s7))) * (1.0f / (float)V_NODES);
}

// ---------------------------------------------------------------------------
extern "C" void kernel_launch(void* const* d_in, const int* in_sizes, int n_in,
                              void* d_out, int out_size) {
    const float* W = (const float*)d_in[0];
    const float* f = (const float*)d_in[1];
    float* out = (float*)d_out;

    fused_kernel<<<GRID, 256>>>(W, f);
    reduce_kernel<<<(NK * D_F + 255) / 256, 256>>>(out);
}

// round 8
// speedup vs baseline: 1.6158x; 1.6158x over previous
#include <cuda_runtime.h>

#define V_NODES 2048
#define D_F     128
#define NBLK    128            // scatter blocks
#define NPB     16             // nodes per scatter block
#define NK      73             // 1 + 8 + 64 output coefficient rows
#define NOUT    (NK * D_F)     // 9344
#define CHUNKS  256            // row chunks for degree partial sums
#define ROWS_PER 8             // rows per chunk
#define RED_SLICES 8           // reduce: blocks per i-range (each sums 16 partials)
#define RED_IBLK 37            // ceil(NOUT/256)

// Scratch (static device globals — no allocation allowed)
__device__ float g_degp[CHUNKS * V_NODES];     // per-chunk column partial sums
__device__ float g_partial[NBLK * NK * D_F];   // block-major scattering partials

// ---------------------------------------------------------------------------
// Kernel 1: column partial sums of W (symmetric => column sum == row sum).
// 512 blocks x 256 threads. Blocks 0..36 also zero the output buffer (the
// kernel boundary orders this before reduce_kernel's atomics).
// ---------------------------------------------------------------------------
__global__ void __launch_bounds__(256) deg_part_kernel(const float* __restrict__ W,
                                                       float* __restrict__ out) {
    const int g  = blockIdx.x & 1;
    const int rc = blockIdx.x >> 1;
    const int c4 = g * 256 + threadIdx.x;          // float4 column index [0,512)

    if (blockIdx.x < RED_IBLK) {
        int i = blockIdx.x * 256 + threadIdx.x;
        if (i < NOUT) out[i] = 0.f;
    }

    const float4* base = (const float4*)W + (size_t)rc * ROWS_PER * 512 + c4;

    float4 v0 = base[0 * 512];
    float4 v1 = base[1 * 512];
    float4 v2 = base[2 * 512];
    float4 v3 = base[3 * 512];
    float4 v4 = base[4 * 512];
    float4 v5 = base[5 * 512];
    float4 v6 = base[6 * 512];
    float4 v7 = base[7 * 512];

    float4 a;
    a.x = ((v0.x + v1.x) + (v2.x + v3.x)) + ((v4.x + v5.x) + (v6.x + v7.x));
    a.y = ((v0.y + v1.y) + (v2.y + v3.y)) + ((v4.y + v5.y) + (v6.y + v7.y));
    a.z = ((v0.z + v1.z) + (v2.z + v3.z)) + ((v4.z + v5.z) + (v6.z + v7.z));
    a.w = ((v0.w + v1.w) + (v2.w + v3.w)) + ((v4.w + v5.w) + (v6.w + v7.w));

    ((float4*)(g_degp + (size_t)rc * V_NODES))[c4] = a;
}

// ---------------------------------------------------------------------------
// Kernel 2: finalize degrees, compute filter responses, accumulate the 73
// scattering coefficients. 128 blocks x 256 threads; thread = (half, d).
// ---------------------------------------------------------------------------
__global__ void __launch_bounds__(256) scat_kernel(const float* __restrict__ f) {
    __shared__ float lam_s[8][NPB];
    __shared__ float deg_sh[NPB];
    __shared__ float comb[NK][D_F];

    const int b = blockIdx.x;
    const int tid = threadIdx.x;
    const int half = tid >> 7;       // 0 or 1
    const int d = tid & 127;         // feature index

    // --- prologue: reduce 256 degree partials per node (16 lanes per node) ---
    {
        const int n = tid >> 4;      // node within tile [0,16)
        const int sub = tid & 15;
        float s = 0.f;
#pragma unroll
        for (int k = 0; k < 16; k++)
            s += g_degp[(size_t)(sub + 16 * k) * V_NODES + b * NPB + n];
#pragma unroll
        for (int off = 8; off; off >>= 1)
            s += __shfl_down_sync(0xffffffffu, s, off, 16);
        if (sub == 0) deg_sh[n] = s;
    }
    __syncthreads();

    if (tid < NPB) {
        float dg = deg_sh[tid];
        float inv = 1.0f / fmaxf(1.0f, dg);       // dhalf^2 with clamp
        float E = fabsf(dg * inv);                // |eigenvalue| for this node
        float logE = logf(E);
        const float Ac = 0.34657359027997264f;    // A = 3*ln(2)/6
        float s = 1.125f;                         // (R/2)*sum(d^2) + (R/2)*d0^2
#pragma unroll
        for (int j = 2; j <= 8; j++) {
            float x = logE - Ac * (float)(j - 1) * (1.0f / 3.0f);
            float w = 0.0f;
            if (x > -Ac && x <= 0.0f)
                w = 0.5f - 0.5f * cosf(x * (6.283185307179586f / Ac));
            lam_s[j - 1][tid] = w;
            s -= w * w;
        }
        lam_s[0][tid] = sqrtf(fmaxf(s, 0.0f));    // scaling function
    }
    __syncthreads();

    // Each half handles 8 nodes x 1 feature per thread.
    const int n0 = half * 8;
    float fv[8];
#pragma unroll
    for (int n = 0; n < 8; n++)
        fv[n] = f[(size_t)(b * NPB + n0 + n) * D_F + d];

    float acc[NK];
#pragma unroll
    for (int k = 0; k < NK; k++) acc[k] = 0.f;

#pragma unroll
    for (int n = 0; n < 8; n++) {
        float v = fv[n];
        float af = fabsf(v);
        acc[0] += v;
        float l[8];
#pragma unroll
        for (int j = 0; j < 8; j++) l[j] = lam_s[j][n0 + n];   // smem broadcast
#pragma unroll
        for (int j = 0; j < 8; j++) acc[1 + j] += l[j] * af;
#pragma unroll
        for (int j1 = 0; j1 < 8; j1++) {
            float t = l[j1] * af;
#pragma unroll
            for (int j2 = 0; j2 < 8; j2++)
                acc[9 + j1 * 8 + j2] += l[j2] * t;
        }
    }

    // Combine halves through smem, half 1 stores.
    if (half == 0) {
#pragma unroll
        for (int k = 0; k < NK; k++) comb[k][d] = acc[k];
    }
    __syncthreads();
    if (half == 1) {
        float* p = g_partial + (size_t)b * (NK * D_F) + d;
#pragma unroll
        for (int k = 0; k < NK; k++)
            p[k * D_F] = acc[k] + comb[k][d];
    }
}

// ---------------------------------------------------------------------------
// Kernel 3: 296 blocks; block (ig, bg) sums 16 of the 128 block-partials for
// 256 outputs, then atomicAdds into out (8 colliding adds per address).
// 16 independent coalesced loads/thread -> latency hidden by 75K threads.
// ---------------------------------------------------------------------------
__global__ void __launch_bounds__(256) reduce_kernel(float* __restrict__ out) {
    const int ig = blockIdx.x % RED_IBLK;
    const int bg = blockIdx.x / RED_IBLK;
    const int i = ig * 256 + threadIdx.x;
    if (i >= NOUT) return;

    const float* p = g_partial + (size_t)bg * 16 * NOUT + i;
    float s0 = 0.f, s1 = 0.f, s2 = 0.f, s3 = 0.f;
    float s4 = 0.f, s5 = 0.f, s6 = 0.f, s7 = 0.f;
    s0 = p[0 * NOUT] + p[8 * NOUT];
    s1 = p[1 * NOUT] + p[9 * NOUT];
    s2 = p[2 * NOUT] + p[10 * NOUT];
    s3 = p[3 * NOUT] + p[11 * NOUT];
    s4 = p[4 * NOUT] + p[12 * NOUT];
    s5 = p[5 * NOUT] + p[13 * NOUT];
    s6 = p[6 * NOUT] + p[14 * NOUT];
    s7 = p[7 * NOUT] + p[15 * NOUT];
    float s = (((s0 + s1) + (s2 + s3)) + ((s4 + s5) + (s6 + s7)));
    atomicAdd(out + i, s * (1.0f / (float)V_NODES));
}

// ---------------------------------------------------------------------------
extern "C" void kernel_launch(void* const* d_in, const int* in_sizes, int n_in,
                              void* d_out, int out_size) {
    const float* W = (const float*)d_in[0];
    const float* f = (const float*)d_in[1];
    float* out = (float*)d_out;

    deg_part_kernel<<<2 * CHUNKS, 256>>>(W, out);
    scat_kernel<<<NBLK, 256>>>(f);
    reduce_kernel<<<RED_IBLK * RED_SLICES, 256>>>(out);
}